// round 13
// baseline (speedup 1.0000x reference)
#include <cuda_runtime.h>
#include <math.h>

#define HH 128
#define WW 128
#define SAT_STRIDE 132           // row stride in floats (mult of 4; data cols 4..131)
#define MAX_PATCH 8192
#define MAX_C 2048

// Scratch (no allocations allowed).
__device__ float g_outT[(size_t)MAX_C * MAX_PATCH];   // [C][N] transposed
__device__ unsigned g_bar = 0;   // monotone ticket barrier (replay-safe)

// ---------------------------------------------------------------------------
// Inline patch-coordinate math, bit-exact vs. the reference:
//   n = i * nrois + r ;  round == rintf (round-half-even == jnp.round)
// ---------------------------------------------------------------------------
__device__ __forceinline__ void patch_coords(
    const float4* __restrict__ roi4, int n, int nrois, int p,
    int4& q, float& inv) {
    int i = n / nrois;     // patch index within roi
    int r = n - i * nrois; // roi index

    float4 rb = roi4[r];
    float xmin = rb.x, ymin = rb.y, xmax = rb.z, ymax = rb.w;

    float ix = (float)(i % p);
    float iy = (float)(i / p);
    float pf = (float)p;

    float wstep = __fdiv_rn(__fadd_rn(xmax, -xmin), pf);
    float hstep = __fdiv_rn(__fadd_rn(ymax, -ymin), pf);

    float ax = __fadd_rn(xmin, __fmul_rn(ix, wstep));
    float ay = __fadd_rn(ymin, __fmul_rn(iy, hstep));

    int x0 = (int)rintf(ax);
    int y0 = (int)rintf(ay);
    int x1 = (int)rintf(__fadd_rn(ax, wstep));
    int y1 = (int)rintf(__fadd_rn(ay, hstep));

    // Reference divides by the RAW (unclamped) count.
    float cnt = (float)((y1 - y0) * (x1 - x0));
    inv = 1.0f / fmaxf(cnt, 1.0f);

    // Clamp only for safe SAT indexing.
    x0 = min(max(x0, 0), WW);  x1 = min(max(x1, 0), WW);
    y0 = min(max(y0, 0), HH);  y1 = min(max(y1, 0), HH);
    q = make_int4(x0, y0, x1, y1);
}

// ---------------------------------------------------------------------------
// Single fused persistent kernel.
//   Phase A: each CTA loops over channels (c = bid, bid+G, ...): build SAT
//            in smem, gather all patches, write coalesced g_outT[c][n].
//   Device-wide ticket barrier (grid co-resident by construction: G comes
//            from the occupancy API on the host).
//   Phase B: 64x64 transpose tiles g_outT[C][N] -> out[N][C], distributed
//            over the same resident CTAs. Kills the ~5us second-kernel
//            launch floor.
// ---------------------------------------------------------------------------
__global__ void __launch_bounds__(256, 3) fused_roi_kernel(
    const float* __restrict__ fm, const float* __restrict__ roi,
    float* __restrict__ out, int C, int N, int nrois, int p, int G) {
    extern __shared__ float sat[];   // HH * SAT_STRIDE floats = 67584 B

    const int tid  = threadIdx.x;
    const int warp = tid >> 5;
    const int lane = tid & 31;
    const float4* roi4 = reinterpret_cast<const float4*>(roi);

    // ===================== Phase A: SAT pooling per channel ================
    for (int c = blockIdx.x; c < C; c += G) {
        // --- fused high-MLP load + row prefix scan ---
        const float4* src =
            reinterpret_cast<const float4*>(fm + (size_t)c * HH * WW);
        #pragma unroll
        for (int half = 0; half < 2; half++) {
            const int rbase = warp * 16 + half * 8;
            float4 v[8];
            #pragma unroll
            for (int k = 0; k < 8; k++)               // 8 LDGs in flight
                v[k] = src[(rbase + k) * (WW / 4) + lane];
            #pragma unroll
            for (int k = 0; k < 8; k++) {             // independent scans
                float4 t = v[k];
                t.y += t.x; t.z += t.y; t.w += t.z;   // intra-quad scan
                float s = t.w;
                #pragma unroll
                for (int d = 1; d < 32; d <<= 1) {    // warp scan
                    float u = __shfl_up_sync(0xffffffffu, s, d);
                    if (lane >= d) s += u;
                }
                float excl = s - t.w;
                t.x += excl; t.y += excl; t.z += excl; t.w += excl;
                *reinterpret_cast<float4*>(
                    &sat[(rbase + k) * SAT_STRIDE + 4 + lane * 4]) = t;
            }
        }
        if (tid < HH) sat[tid * SAT_STRIDE + 3] = 0.0f;  // x=-1 boundary
        __syncthreads();

        // --- column scan, 2-way split ---
        {
            int col  = tid & 127;
            int half = tid >> 7;
            float* ptr = &sat[(half * 64) * SAT_STRIDE + 4 + col];
            float acc = 0.0f;
            #pragma unroll 8
            for (int y = 0; y < 64; y++) {
                acc += ptr[y * SAT_STRIDE];
                ptr[y * SAT_STRIDE] = acc;
            }
        }
        __syncthreads();

        // --- gather, coalesced STG.128 into g_outT[c][*] ---
        const float* r63 = &sat[63 * SAT_STRIDE + 3];
        float* orow = &g_outT[(size_t)c * N];
        if ((N & 3) == 0) {
            for (int n4 = tid * 4; n4 < N; n4 += 1024) {
                float res[4];
                #pragma unroll
                for (int k = 0; k < 4; k++) {
                    int4 q; float inv;
                    patch_coords(roi4, n4 + k, nrois, p, q, inv);
                    int yb = max(q.w, 1) - 1;
                    int ya = max(q.y, 1) - 1;
                    float mbot  = (q.y > 0) ? 1.0f : 0.0f;
                    float vmask = (q.z > q.x && q.w > q.y) ? 1.0f : 0.0f;
                    float d63 = r63[q.z] - r63[q.x];
                    const float* rb = &sat[yb * SAT_STRIDE + 3];
                    const float* ra = &sat[ya * SAT_STRIDE + 3];
                    float sb = (rb[q.z] - rb[q.x]) + ((yb >= 64) ? d63 : 0.0f);
                    float sa = (ra[q.z] - ra[q.x]) + ((ya >= 64) ? d63 : 0.0f);
                    res[k] = (sb - mbot * sa) * vmask * inv;
                }
                *reinterpret_cast<float4*>(&orow[n4]) =
                    make_float4(res[0], res[1], res[2], res[3]);
            }
        } else {
            for (int n = tid; n < N; n += 256) {
                int4 q; float inv;
                patch_coords(roi4, n, nrois, p, q, inv);
                int yb = max(q.w, 1) - 1;
                int ya = max(q.y, 1) - 1;
                float mbot  = (q.y > 0) ? 1.0f : 0.0f;
                float vmask = (q.z > q.x && q.w > q.y) ? 1.0f : 0.0f;
                float d63 = r63[q.z] - r63[q.x];
                const float* rb = &sat[yb * SAT_STRIDE + 3];
                const float* ra = &sat[ya * SAT_STRIDE + 3];
                float sb = (rb[q.z] - rb[q.x]) + ((yb >= 64) ? d63 : 0.0f);
                float sa = (ra[q.z] - ra[q.x]) + ((ya >= 64) ? d63 : 0.0f);
                orow[n] = (sb - mbot * sa) * vmask * inv;
            }
        }
        __syncthreads();    // smem reused next channel iteration
    }

    // ===================== Device-wide barrier =============================
    // Monotone ticket barrier: launch k's tickets land in [kG,(k+1)G);
    // all CTAs of this launch proceed once g_bar reaches (k+1)G. No reset
    // needed across graph replays. Co-residency guaranteed by host-side
    // occupancy-derived G.
    if (tid == 0) {
        __threadfence();                       // publish g_outT writes
        unsigned ticket = atomicAdd(&g_bar, 1u);
        unsigned target = (ticket / (unsigned)G + 1u) * (unsigned)G;
        while (*(volatile unsigned*)&g_bar < target) __nanosleep(64);
        __threadfence();                       // acquire
    }
    __syncthreads();

    // ===================== Phase B: transpose ==============================
    if ((N % 64 == 0) && (C % 64 == 0)) {
        const int tilesN = N / 64;
        const int tiles  = tilesN * (C / 64);
        float (*tile)[65] = reinterpret_cast<float(*)[65]>(sat);
        for (int t = blockIdx.x; t < tiles; t += G) {
            const int nBase = (t % tilesN) * 64;
            const int cBase = (t / tilesN) * 64;
            // Load: float4 rows of g_outT.
            {
                const int n4 = (tid & 15) * 4;
                const int cl = tid >> 4;           // 0..15
                #pragma unroll
                for (int k = 0; k < 4; k++) {
                    int cc = cl + k * 16;
                    float4 v = *reinterpret_cast<const float4*>(
                        &g_outT[(size_t)(cBase + cc) * N + nBase + n4]);
                    tile[cc][n4 + 0] = v.x;
                    tile[cc][n4 + 1] = v.y;
                    tile[cc][n4 + 2] = v.z;
                    tile[cc][n4 + 3] = v.w;
                }
            }
            __syncthreads();
            // Store: float4 rows of out.
            {
                const int c4 = (tid & 15) * 4;
                const int nl = tid >> 4;           // 0..15
                #pragma unroll
                for (int k = 0; k < 4; k++) {
                    int nn = nl + k * 16;
                    float4 v = make_float4(tile[c4 + 0][nn], tile[c4 + 1][nn],
                                           tile[c4 + 2][nn], tile[c4 + 3][nn]);
                    *reinterpret_cast<float4*>(
                        &out[(size_t)(nBase + nn) * C + cBase + c4]) = v;
                }
            }
            __syncthreads();
        }
    } else {
        // Generic fallback (not hit for this shape): elementwise transposed copy.
        size_t total = (size_t)N * C;
        for (size_t idx = (size_t)blockIdx.x * 256 + tid; idx < total;
             idx += (size_t)G * 256) {
            int nn = (int)(idx / C);
            int cc = (int)(idx - (size_t)nn * C);
            out[idx] = g_outT[(size_t)cc * N + nn];
        }
    }
}

// ---------------------------------------------------------------------------
extern "C" void kernel_launch(void* const* d_in, const int* in_sizes, int n_in,
                              void* d_out, int out_size) {
    const float* fm  = (const float*)d_in[0];
    const float* roi = (const float*)d_in[1];
    float* out = (float*)d_out;

    int C     = in_sizes[0] / (HH * WW);
    int nrois = in_sizes[1] / 4;
    int N     = out_size / C;
    int patch_num = N / nrois;
    int p = (int)(sqrtf((float)patch_num) + 0.5f);

    size_t smem = (size_t)HH * SAT_STRIDE * sizeof(float);
    cudaFuncSetAttribute(fused_roi_kernel,
                         cudaFuncAttributeMaxDynamicSharedMemorySize,
                         (int)smem);

    int dev = 0, numSMs = 148;
    cudaGetDevice(&dev);
    cudaDeviceGetAttribute(&numSMs, cudaDevAttrMultiProcessorCount, dev);
    int bpm = 0;
    cudaOccupancyMaxActiveBlocksPerMultiprocessor(
        &bpm, fused_roi_kernel, 256, smem);
    if (bpm < 1) bpm = 1;
    int G = bpm * numSMs;
    if (G > C) G = C;

    fused_roi_kernel<<<G, 256, smem>>>(fm, roi, out, C, N, nrois, p, G);
}